// round 1
// baseline (speedup 1.0000x reference)
#include <cuda_runtime.h>

#define NB 4
#define CIN 256
#define CH 128      // C2
#define NT 16
#define NS 256      // spatial per frame
#define NP 4096     // T*S

// Scratch (device globals: no allocation allowed)
__device__ float g_Q [(size_t)NB*CH*NP];  // [b][c][p]   (channel-major)
__device__ float g_M [(size_t)NB*CH*NP];  // [b][c][p]
__device__ float g_Vt[(size_t)NB*NP*CH];  // [b][p][c]   (position-major)

typedef unsigned long long u64;
union F2 { u64 u; float f[2]; };

__device__ __forceinline__ u64 pk2(float x, float y){
    u64 r; asm("mov.b64 %0, {%1, %2};" : "=l"(r) : "f"(x), "f"(y)); return r;
}
__device__ __forceinline__ void fma2(u64 &d, u64 a, u64 b){
    asm("fma.rn.f32x2 %0, %1, %2, %0;" : "+l"(d) : "l"(a), "l"(b));
}
__device__ __forceinline__ void mul2(u64 &d, u64 a){
    asm("mul.rn.f32x2 %0, %0, %1;" : "+l"(d) : "l"(a));
}

// ---------------------------------------------------------------------------
// Kernel A: pointwise projections. One CTA = one (batch, proj, 128-pos tile).
// out[p,o] = sum_c x[b,c,p] * W[o,c];  K=256 in 4 chunks of 64.
// ---------------------------------------------------------------------------
__global__ void __launch_bounds__(256, 2) proj_kernel(
    const float* __restrict__ x,
    const float* __restrict__ Wq,
    const float* __restrict__ Wm,
    const float* __restrict__ Wv,
    float* __restrict__ vout)
{
    extern __shared__ float sm[];
    float* xs = sm;            // [64 c][128 p]
    float* ws = sm + 64*128;   // [64 c][128 o]

    const int b    = blockIdx.z;
    const int proj = blockIdx.y;
    const int p0   = blockIdx.x * 128;
    const float* W = (proj == 0) ? Wq : ((proj == 1) ? Wm : Wv);

    const int tid = threadIdx.x;
    const int ty = tid >> 4;   // 0..15 -> p groups of 8 (as 4 pairs)
    const int tx = tid & 15;   // 0..15 -> o groups of 8

    u64 acc[4][8];
    #pragma unroll
    for (int i = 0; i < 4; i++)
        #pragma unroll
        for (int j = 0; j < 8; j++) acc[i][j] = 0ull;

    for (int ck = 0; ck < 4; ck++) {
        if (ck) __syncthreads();
        // xs fill: coalesced float4 per row of x
        #pragma unroll
        for (int i = 0; i < 8; i++) {
            int idx = i*256 + tid;
            int r = idx >> 5, c4 = idx & 31;
            ((float4*)xs)[idx] =
                ((const float4*)(x + ((size_t)(b*CIN + ck*64 + r))*NP + p0))[c4];
        }
        // ws fill (transpose W[o][c] -> ws[c][o]); conflict-free smem stores
        #pragma unroll
        for (int i = 0; i < 32; i++) {
            int idx = i*256 + tid;
            int c = idx >> 7, o = idx & 127;
            ws[c*128 + o] = W[o*CIN + ck*64 + c];
        }
        __syncthreads();

        #pragma unroll 4
        for (int cc = 0; cc < 64; cc++) {
            const float* xr = xs + cc*128 + 8*ty;
            u64 a0 = *(const u64*)(xr);
            u64 a1 = *(const u64*)(xr + 2);
            u64 a2 = *(const u64*)(xr + 4);
            u64 a3 = *(const u64*)(xr + 6);
            const float* wr = ws + cc*128 + 8*tx;
            float4 b0 = *(const float4*)(wr);
            float4 b1 = *(const float4*)(wr + 4);
            u64 pb[8];
            pb[0]=pk2(b0.x,b0.x); pb[1]=pk2(b0.y,b0.y);
            pb[2]=pk2(b0.z,b0.z); pb[3]=pk2(b0.w,b0.w);
            pb[4]=pk2(b1.x,b1.x); pb[5]=pk2(b1.y,b1.y);
            pb[6]=pk2(b1.z,b1.z); pb[7]=pk2(b1.w,b1.w);
            #pragma unroll
            for (int j = 0; j < 8; j++) {
                fma2(acc[0][j], a0, pb[j]);
                fma2(acc[1][j], a1, pb[j]);
                fma2(acc[2][j], a2, pb[j]);
                fma2(acc[3][j], a3, pb[j]);
            }
        }
    }

    const int obase = 8*tx;
    const int pbase = p0 + 8*ty;

    if (proj < 2) {
        float* g = (proj == 0) ? g_Q : g_M;
        #pragma unroll
        for (int j = 0; j < 8; j++) {
            int o = obase + j;
            float* go = g + ((size_t)b*CH + o)*NP + pbase;
            #pragma unroll
            for (int pi = 0; pi < 4; pi++) {
                F2 u; u.u = acc[pi][j];
                go[2*pi] = u.f[0]; go[2*pi + 1] = u.f[1];
            }
        }
    } else {
        // V: position-major scratch (coalesced float4) + V output region
        #pragma unroll
        for (int pi = 0; pi < 4; pi++) {
            #pragma unroll
            for (int h = 0; h < 2; h++) {
                int p = pbase + 2*pi + h;
                float tmp[8];
                #pragma unroll
                for (int j = 0; j < 8; j++) { F2 u; u.u = acc[pi][j]; tmp[j] = u.f[h]; }
                float* gv = g_Vt + ((size_t)b*NP + p)*CH + obase;
                *(float4*)gv       = make_float4(tmp[0], tmp[1], tmp[2], tmp[3]);
                *(float4*)(gv + 4) = make_float4(tmp[4], tmp[5], tmp[6], tmp[7]);
            }
        }
        #pragma unroll
        for (int j = 0; j < 8; j++) {
            int o = obase + j;
            float* go = vout + ((size_t)b*CH + o)*NP + pbase;
            #pragma unroll
            for (int pi = 0; pi < 4; pi++) {
                F2 u; u.u = acc[pi][j];
                go[2*pi] = u.f[0]; go[2*pi + 1] = u.f[1];
            }
        }
    }
}

// ---------------------------------------------------------------------------
// Kernel B: fused attention per (batch, key-frame, 128-query tile).
// S = (Q*scale)^T M  -> exact softmax over 256 keys -> O = P V^T * (1/sum)
// ---------------------------------------------------------------------------
__global__ void __launch_bounds__(256, 1) attn_kernel(float* __restrict__ outR)
{
    extern __shared__ float sm[];
    float* Qs  = sm;                 // [128 c][128 q]   16384 f
    float* MVs = sm + 16384;         // [128 c][64 k] or [64 s][128 c]  8192 f
    float* Ss  = sm + 16384 + 8192;  // [256 s][128 q]   32768 f
    float* rs  = Ss + 32768;         // [128]  1/rowsum

    const int qtile = blockIdx.x;    // 0..31
    const int t     = blockIdx.y;    // key frame
    const int b     = blockIdx.z;
    const int q0    = qtile * 128;

    const int tid = threadIdx.x;
    const int ty = tid >> 4;         // q groups
    const int tx = tid & 15;         // k / c groups
    const float scale = 0.08838834764831845f;  // 1/sqrt(128)

    // Phase 0: Q tile (scaled) into smem, c-major rows
    #pragma unroll
    for (int i = 0; i < 16; i++) {
        int idx = i*256 + tid;
        int c = idx >> 5, c4 = idx & 31;
        float4 v = ((const float4*)(g_Q + ((size_t)b*CH + c)*NP + q0))[c4];
        v.x *= scale; v.y *= scale; v.z *= scale; v.w *= scale;
        ((float4*)Qs)[idx] = v;
    }

    // Phase 1: S = Q^T M, keys in 4 chunks of 64. S stored [s][q].
    for (int kc = 0; kc < 4; kc++) {
        __syncthreads();
        #pragma unroll
        for (int i = 0; i < 8; i++) {
            int idx = i*256 + tid;
            int c = idx >> 4, k4 = idx & 15;
            ((float4*)MVs)[idx] =
                ((const float4*)(g_M + ((size_t)b*CH + c)*NP + t*NS + kc*64))[k4];
        }
        __syncthreads();

        u64 acc[4][4];
        #pragma unroll
        for (int i = 0; i < 4; i++)
            #pragma unroll
            for (int j = 0; j < 4; j++) acc[i][j] = 0ull;

        #pragma unroll 4
        for (int cc = 0; cc < 128; cc++) {
            const float* qr = Qs + cc*128 + 8*ty;
            u64 a0 = *(const u64*)(qr);
            u64 a1 = *(const u64*)(qr + 2);
            u64 a2 = *(const u64*)(qr + 4);
            u64 a3 = *(const u64*)(qr + 6);
            float4 bv = *(const float4*)(MVs + cc*64 + 4*tx);
            u64 pb0 = pk2(bv.x, bv.x);
            u64 pb1 = pk2(bv.y, bv.y);
            u64 pb2 = pk2(bv.z, bv.z);
            u64 pb3 = pk2(bv.w, bv.w);
            fma2(acc[0][0],a0,pb0); fma2(acc[1][0],a1,pb0); fma2(acc[2][0],a2,pb0); fma2(acc[3][0],a3,pb0);
            fma2(acc[0][1],a0,pb1); fma2(acc[1][1],a1,pb1); fma2(acc[2][1],a2,pb1); fma2(acc[3][1],a3,pb1);
            fma2(acc[0][2],a0,pb2); fma2(acc[1][2],a1,pb2); fma2(acc[2][2],a2,pb2); fma2(acc[3][2],a3,pb2);
            fma2(acc[0][3],a0,pb3); fma2(acc[1][3],a1,pb3); fma2(acc[2][3],a2,pb3); fma2(acc[3][3],a3,pb3);
        }
        #pragma unroll
        for (int j = 0; j < 4; j++) {
            float* sp = Ss + (kc*64 + 4*tx + j)*128 + 8*ty;
            ulonglong2 v01; v01.x = acc[0][j]; v01.y = acc[1][j];
            ulonglong2 v23; v23.x = acc[2][j]; v23.y = acc[3][j];
            *(ulonglong2*)(sp)     = v01;
            *(ulonglong2*)(sp + 4) = v23;
        }
    }
    __syncthreads();

    // Phase 2: softmax over s per query; store unnormalized exp, keep 1/sum
    {
        int q = tid >> 1, h = tid & 1;
        float m = -1e30f;
        #pragma unroll 4
        for (int s = 0; s < 128; s++)
            m = fmaxf(m, Ss[(h*128 + s)*128 + q]);
        m = fmaxf(m, __shfl_xor_sync(0xffffffffu, m, 1));
        float sum = 0.f;
        #pragma unroll 4
        for (int s = 0; s < 128; s++) {
            float* p = Ss + (h*128 + s)*128 + q;
            float e = __expf(*p - m);
            *p = e; sum += e;
        }
        sum += __shfl_xor_sync(0xffffffffu, sum, 1);
        if (h == 0) rs[q] = 1.0f / sum;
    }

    // Phase 3: O = P V^T, s in 4 chunks of 64
    u64 acc[4][8];
    #pragma unroll
    for (int i = 0; i < 4; i++)
        #pragma unroll
        for (int j = 0; j < 8; j++) acc[i][j] = 0ull;

    for (int sc = 0; sc < 4; sc++) {
        __syncthreads();
        #pragma unroll
        for (int i = 0; i < 8; i++) {
            int idx = i*256 + tid;
            int sr = idx >> 5, c4 = idx & 31;
            ((float4*)MVs)[idx] =
                ((const float4*)(g_Vt + ((size_t)b*NP + t*NS + sc*64 + sr)*CH))[c4];
        }
        __syncthreads();

        #pragma unroll 2
        for (int ss = 0; ss < 64; ss++) {
            const float* pr = Ss + (sc*64 + ss)*128 + 8*ty;
            u64 a0 = *(const u64*)(pr);
            u64 a1 = *(const u64*)(pr + 2);
            u64 a2 = *(const u64*)(pr + 4);
            u64 a3 = *(const u64*)(pr + 6);
            const float* vr = MVs + ss*128 + 8*tx;
            float4 b0 = *(const float4*)(vr);
            float4 b1 = *(const float4*)(vr + 4);
            u64 pb[8];
            pb[0]=pk2(b0.x,b0.x); pb[1]=pk2(b0.y,b0.y);
            pb[2]=pk2(b0.z,b0.z); pb[3]=pk2(b0.w,b0.w);
            pb[4]=pk2(b1.x,b1.x); pb[5]=pk2(b1.y,b1.y);
            pb[6]=pk2(b1.z,b1.z); pb[7]=pk2(b1.w,b1.w);
            #pragma unroll
            for (int j = 0; j < 8; j++) {
                fma2(acc[0][j], a0, pb[j]);
                fma2(acc[1][j], a1, pb[j]);
                fma2(acc[2][j], a2, pb[j]);
                fma2(acc[3][j], a3, pb[j]);
            }
        }
    }

    // Epilogue: normalize by 1/rowsum and write R[b][c][t_key][t_q][hw]
    u64 rp[4];
    #pragma unroll
    for (int pi = 0; pi < 4; pi++) rp[pi] = *(const u64*)(rs + 8*ty + 2*pi);
    #pragma unroll
    for (int j = 0; j < 8; j++)
        #pragma unroll
        for (int pi = 0; pi < 4; pi++) mul2(acc[pi][j], rp[pi]);

    const int tq  = qtile >> 1;
    const int hw0 = (qtile & 1) * 128;
    #pragma unroll
    for (int j = 0; j < 8; j++) {
        int c = 8*tx + j;
        float* po = outR + ((((size_t)b*CH + c)*NT + t)*NT + tq)*NS + hw0 + 8*ty;
        ulonglong2 w0; w0.x = acc[0][j]; w0.y = acc[1][j];
        ulonglong2 w1; w1.x = acc[2][j]; w1.y = acc[3][j];
        *(ulonglong2*)(po)     = w0;
        *(ulonglong2*)(po + 4) = w1;
    }
}

// ---------------------------------------------------------------------------
extern "C" void kernel_launch(void* const* d_in, const int* in_sizes, int n_in,
                              void* d_out, int out_size)
{
    const float* x  = (const float*)d_in[0];
    const float* Wq = (const float*)d_in[1];
    const float* Wm = (const float*)d_in[2];
    const float* Wv = (const float*)d_in[3];
    float* out = (float*)d_out;

    const size_t R_SIZE = (size_t)NB * CH * NT * NT * NS;  // 33,554,432
    float* vout = out + R_SIZE;

    const int PROJ_SMEM = 64 * 128 * 2 * 4;                 // 65536 B
    const int ATTN_SMEM = (16384 + 8192 + 32768 + 128) * 4; // 229888 B

    cudaFuncSetAttribute(proj_kernel, cudaFuncAttributeMaxDynamicSharedMemorySize, PROJ_SMEM);
    cudaFuncSetAttribute(attn_kernel, cudaFuncAttributeMaxDynamicSharedMemorySize, ATTN_SMEM);

    proj_kernel<<<dim3(32, 3, NB), 256, PROJ_SMEM>>>(x, Wq, Wm, Wv, vout);
    attn_kernel<<<dim3(32, NT, NB), 256, ATTN_SMEM>>>(out);
}

// round 3
// speedup vs baseline: 2.0557x; 2.0557x over previous
#include <cuda_runtime.h>

#define NB 4
#define CIN 256
#define CH 128      // C2
#define NT 16
#define NS 256      // spatial per frame
#define NP 4096     // T*S

// Scratch (device globals: no allocation allowed).
// Position-major [b][p][c], tf32-rounded. Q pre-scaled by 1/sqrt(128).
__device__ float g_Qt[(size_t)NB*NP*CH];
__device__ float g_Mt[(size_t)NB*NP*CH];
__device__ float g_Vt[(size_t)NB*NP*CH];

typedef unsigned long long u64;
typedef unsigned int u32;
union F2 { u64 u; float f[2]; };

__device__ __forceinline__ u64 pk2(float x, float y){
    u64 r; asm("mov.b64 %0, {%1, %2};" : "=l"(r) : "f"(x), "f"(y)); return r;
}
__device__ __forceinline__ void fma2(u64 &d, u64 a, u64 b){
    asm("fma.rn.f32x2 %0, %1, %2, %0;" : "+l"(d) : "l"(a), "l"(b));
}
__device__ __forceinline__ float cvt_tf32(float x){
    u32 r; asm("cvt.rna.tf32.f32 %0, %1;" : "=r"(r) : "f"(x));
    return __uint_as_float(r);
}
__device__ __forceinline__ u32 fb(float x){ return __float_as_uint(x); }

// m16n8k8 tf32 mma: D += A*B  (row.col, f32 accum). Generic sm_80+ PTX.
__device__ __forceinline__ void mma8(float* d, const u32* a, const u32* b){
    asm volatile("mma.sync.aligned.m16n8k8.row.col.f32.tf32.tf32.f32 "
        "{%0,%1,%2,%3}, {%4,%5,%6,%7}, {%8,%9}, {%0,%1,%2,%3};"
        : "+f"(d[0]), "+f"(d[1]), "+f"(d[2]), "+f"(d[3])
        : "r"(a[0]), "r"(a[1]), "r"(a[2]), "r"(a[3]), "r"(b[0]), "r"(b[1]));
}

// ---------------------------------------------------------------------------
// Kernel A: pointwise projections (fp32 FFMA, exact).
// Q,M -> g_Qt/g_Mt [b][p][c] tf32 (Q pre-scaled). V -> vout [b][c][p] exact
// fp32 (the V output) AND g_Vt [b][p][c] tf32 (B operand for PV GEMM).
// ---------------------------------------------------------------------------
__global__ void __launch_bounds__(256, 2) proj_kernel(
    const float* __restrict__ x,
    const float* __restrict__ Wq,
    const float* __restrict__ Wm,
    const float* __restrict__ Wv,
    float* __restrict__ vout)
{
    extern __shared__ float sm[];
    float* xs = sm;            // [64 c][128 p]
    float* ws = sm + 64*128;   // [64 c][128 o]

    const int b    = blockIdx.z;
    const int proj = blockIdx.y;
    const int p0   = blockIdx.x * 128;
    const float* W = (proj == 0) ? Wq : ((proj == 1) ? Wm : Wv);

    const int tid = threadIdx.x;
    const int ty = tid >> 4;
    const int tx = tid & 15;

    u64 acc[4][8];
    #pragma unroll
    for (int i = 0; i < 4; i++)
        #pragma unroll
        for (int j = 0; j < 8; j++) acc[i][j] = 0ull;

    for (int ck = 0; ck < 4; ck++) {
        if (ck) __syncthreads();
        #pragma unroll
        for (int i = 0; i < 8; i++) {
            int idx = i*256 + tid;
            int r = idx >> 5, c4 = idx & 31;
            ((float4*)xs)[idx] =
                ((const float4*)(x + ((size_t)(b*CIN + ck*64 + r))*NP + p0))[c4];
        }
        #pragma unroll
        for (int i = 0; i < 32; i++) {
            int idx = i*256 + tid;
            int c = idx >> 7, o = idx & 127;
            ws[c*128 + o] = W[o*CIN + ck*64 + c];
        }
        __syncthreads();

        #pragma unroll 4
        for (int cc = 0; cc < 64; cc++) {
            const float* xr = xs + cc*128 + 8*ty;
            u64 a0 = *(const u64*)(xr);
            u64 a1 = *(const u64*)(xr + 2);
            u64 a2 = *(const u64*)(xr + 4);
            u64 a3 = *(const u64*)(xr + 6);
            const float* wr = ws + cc*128 + 8*tx;
            float4 b0 = *(const float4*)(wr);
            float4 b1 = *(const float4*)(wr + 4);
            u64 pb[8];
            pb[0]=pk2(b0.x,b0.x); pb[1]=pk2(b0.y,b0.y);
            pb[2]=pk2(b0.z,b0.z); pb[3]=pk2(b0.w,b0.w);
            pb[4]=pk2(b1.x,b1.x); pb[5]=pk2(b1.y,b1.y);
            pb[6]=pk2(b1.z,b1.z); pb[7]=pk2(b1.w,b1.w);
            #pragma unroll
            for (int j = 0; j < 8; j++) {
                fma2(acc[0][j], a0, pb[j]);
                fma2(acc[1][j], a1, pb[j]);
                fma2(acc[2][j], a2, pb[j]);
                fma2(acc[3][j], a3, pb[j]);
            }
        }
    }

    const int obase = 8*tx;
    const int pbase = p0 + 8*ty;

    if (proj == 2) {
        // exact fp32 V output, channel-major
        #pragma unroll
        for (int j = 0; j < 8; j++) {
            int o = obase + j;
            float* go = vout + ((size_t)b*CH + o)*NP + pbase;
            #pragma unroll
            for (int pi = 0; pi < 4; pi++) {
                F2 u; u.u = acc[pi][j];
                go[2*pi] = u.f[0]; go[2*pi + 1] = u.f[1];
            }
        }
        // tf32 position-major copy for the PV GEMM
        #pragma unroll
        for (int pi = 0; pi < 4; pi++) {
            #pragma unroll
            for (int h = 0; h < 2; h++) {
                int p = pbase + 2*pi + h;
                float tmp[8];
                #pragma unroll
                for (int j = 0; j < 8; j++) {
                    F2 u; u.u = acc[pi][j];
                    tmp[j] = cvt_tf32(u.f[h]);
                }
                float* gp = g_Vt + ((size_t)b*NP + p)*CH + obase;
                *(float4*)gp       = make_float4(tmp[0], tmp[1], tmp[2], tmp[3]);
                *(float4*)(gp + 4) = make_float4(tmp[4], tmp[5], tmp[6], tmp[7]);
            }
        }
    } else {
        float* g = proj ? g_Mt : g_Qt;
        const float sc = proj ? 1.0f : 0.08838834764831845f;
        #pragma unroll
        for (int pi = 0; pi < 4; pi++) {
            #pragma unroll
            for (int h = 0; h < 2; h++) {
                int p = pbase + 2*pi + h;
                float tmp[8];
                #pragma unroll
                for (int j = 0; j < 8; j++) {
                    F2 u; u.u = acc[pi][j];
                    tmp[j] = cvt_tf32(sc * u.f[h]);
                }
                float* gp = g + ((size_t)b*NP + p)*CH + obase;
                *(float4*)gp       = make_float4(tmp[0], tmp[1], tmp[2], tmp[3]);
                *(float4*)(gp + 4) = make_float4(tmp[4], tmp[5], tmp[6], tmp[7]);
            }
        }
    }
}

// ---------------------------------------------------------------------------
// Kernel B: mma.sync tf32 attention. 256 threads (8 warps), 1 CTA/SM.
// smem floats: Qs[128q][128c] swizzled @0 (pmax/psum alias here after GEMM1);
//              MV chunk @16384 (M: 64x132 / V: 64x136);
//              Ss[128q][256s] swizzled @25088 (S -> P -> O^T scratch).
// ---------------------------------------------------------------------------
#define QS_F 0
#define MV_F 16384
#define SS_F 25088
#define ATTN_SMEM ((MV_F + 8704 + 32768) * 4)   // 231424 B

__global__ void __launch_bounds__(256, 1) attn_kernel(float* __restrict__ outR)
{
    extern __shared__ float sm[];
    float* Qs   = sm + QS_F;
    float* MV   = sm + MV_F;
    float* Ss   = sm + SS_F;
    float* pmax = sm;          // aliases Qs (dead after GEMM1)
    float* psum = sm + 256;

    const int tid = threadIdx.x;
    const int w = tid >> 5, lane = tid & 31;
    const int g = lane >> 2, tt = lane & 3;
    const int qtile = blockIdx.x, t = blockIdx.y, b = blockIdx.z;
    const int q0 = qtile * 128;

    const int m0 = (w >> 1) * 32;      // warp q-base
    const int n0 = (w & 1) * 32;       // warp s-base within 64-chunk (GEMM1)
    const int c0 = (w & 1) * 64;       // warp c-base (GEMM2)

    // ---- stage Q (tf32, pre-scaled), swizzled [q][c ^ ((q&7)<<2)] ----
    {
        const float4* gq = (const float4*)(g_Qt + ((size_t)b*NP + q0)*CH);
        #pragma unroll
        for (int i = 0; i < 16; i++) {
            int idx = i*256 + tid;
            int q = idx >> 5, c4 = (idx & 31) * 4;
            *(float4*)&Qs[q*128 + (c4 ^ ((q & 7) << 2))] = gq[idx];
        }
    }

    // ---- GEMM1: S[128q x 256s] = Q[128x128] * M^T, 4 key chunks of 64 ----
    const float* gmrow = g_Mt + ((size_t)b*NP + t*NS)*CH;
    for (int sc = 0; sc < 4; sc++) {
        __syncthreads();
        #pragma unroll
        for (int i = 0; i < 8; i++) {
            int idx = i*256 + tid;
            int s = idx >> 5, c4 = (idx & 31) * 4;
            *(float4*)&MV[s*132 + c4] =
                *(const float4*)&gmrow[(size_t)(sc*64 + s)*CH + c4];
        }
        __syncthreads();

        float d[2][4][4];
        #pragma unroll
        for (int mi = 0; mi < 2; mi++)
            #pragma unroll
            for (int ni = 0; ni < 4; ni++)
                #pragma unroll
                for (int r = 0; r < 4; r++) d[mi][ni][r] = 0.f;

        #pragma unroll
        for (int k = 0; k < 16; k++) {
            u32 a[2][4], bbf[4][2];
            #pragma unroll
            for (int mi = 0; mi < 2; mi++) {
                int q = m0 + mi*16 + g;
                int swz = (q & 7) << 2;          // (q+8)&7 == q&7
                int c = k*8 + tt;
                a[mi][0] = fb(Qs[q*128     + (c ^ swz)]);
                a[mi][1] = fb(Qs[(q+8)*128 + (c ^ swz)]);
                a[mi][2] = fb(Qs[q*128     + ((c+4) ^ swz)]);
                a[mi][3] = fb(Qs[(q+8)*128 + ((c+4) ^ swz)]);
            }
            #pragma unroll
            for (int ni = 0; ni < 4; ni++) {
                int s = n0 + ni*8 + g;
                bbf[ni][0] = fb(MV[s*132 + k*8 + tt]);
                bbf[ni][1] = fb(MV[s*132 + k*8 + tt + 4]);
            }
            #pragma unroll
            for (int mi = 0; mi < 2; mi++)
                #pragma unroll
                for (int ni = 0; ni < 4; ni++)
                    mma8(d[mi][ni], a[mi], bbf[ni]);
        }

        // store S fragments (swizzled rows)
        #pragma unroll
        for (int mi = 0; mi < 2; mi++) {
            int q = m0 + mi*16 + g;
            int swz = (q & 7) << 2;
            #pragma unroll
            for (int ni = 0; ni < 4; ni++) {
                int s = sc*64 + n0 + ni*8 + 2*tt;
                *(float2*)&Ss[q*256     + (s ^ swz)] =
                    make_float2(d[mi][ni][0], d[mi][ni][1]);
                *(float2*)&Ss[(q+8)*256 + (s ^ swz)] =
                    make_float2(d[mi][ni][2], d[mi][ni][3]);
            }
        }
    }
    __syncthreads();   // S complete; Qs now dead

    // ---- softmax over 256 keys per q row; P stored back as tf32 ----
    {
        int q = tid & 127, h = tid >> 7;
        int base = q*256;
        int swz = (q & 7) << 2;
        float mx = -3.0e38f;
        #pragma unroll 8
        for (int j = 0; j < 32; j++) {
            float4 v = *(float4*)&Ss[base + ((h*128 + j*4) ^ swz)];
            mx = fmaxf(mx, fmaxf(fmaxf(v.x, v.y), fmaxf(v.z, v.w)));
        }
        pmax[h*128 + q] = mx;
        __syncthreads();
        float gmx = fmaxf(pmax[q], pmax[128 + q]);
        float sum = 0.f;
        #pragma unroll 4
        for (int j = 0; j < 32; j++) {
            int off = base + ((h*128 + j*4) ^ swz);
            float4 v = *(float4*)&Ss[off];
            float e0 = __expf(v.x - gmx), e1 = __expf(v.y - gmx);
            float e2 = __expf(v.z - gmx), e3 = __expf(v.w - gmx);
            sum += (e0 + e1) + (e2 + e3);
            v.x = cvt_tf32(e0); v.y = cvt_tf32(e1);
            v.z = cvt_tf32(e2); v.w = cvt_tf32(e3);
            *(float4*)&Ss[off] = v;
        }
        psum[h*128 + q] = sum;
    }

    // ---- GEMM2: O[128q x 128c] = P[128x256] * V, 4 s-chunks of 64 ----
    float e[2][8][4];
    #pragma unroll
    for (int mi = 0; mi < 2; mi++)
        #pragma unroll
        for (int ni = 0; ni < 8; ni++)
            #pragma unroll
            for (int r = 0; r < 4; r++) e[mi][ni][r] = 0.f;

    const float* gvrow = g_Vt + ((size_t)b*NP + t*NS)*CH;
    for (int sc = 0; sc < 4; sc++) {
        __syncthreads();
        #pragma unroll
        for (int i = 0; i < 8; i++) {
            int idx = i*256 + tid;
            int s = idx >> 5, c4 = (idx & 31) * 4;
            *(float4*)&MV[s*136 + c4] =
                *(const float4*)&gvrow[(size_t)(sc*64 + s)*CH + c4];
        }
        __syncthreads();

        #pragma unroll
        for (int k = 0; k < 8; k++) {
            u32 a[2][4], bbf[8][2];
            #pragma unroll
            for (int mi = 0; mi < 2; mi++) {
                int q = m0 + mi*16 + g;
                int swz = (q & 7) << 2;
                int s = sc*64 + k*8 + tt;
                a[mi][0] = fb(Ss[q*256     + (s ^ swz)]);
                a[mi][1] = fb(Ss[(q+8)*256 + (s ^ swz)]);
                a[mi][2] = fb(Ss[q*256     + ((s+4) ^ swz)]);
                a[mi][3] = fb(Ss[(q+8)*256 + ((s+4) ^ swz)]);
            }
            #pragma unroll
            for (int ni = 0; ni < 8; ni++) {
                int c = c0 + ni*8 + g;
                bbf[ni][0] = fb(MV[(k*8 + tt)*136     + c]);
                bbf[ni][1] = fb(MV[(k*8 + tt + 4)*136 + c]);
            }
            #pragma unroll
            for (int mi = 0; mi < 2; mi++)
                #pragma unroll
                for (int ni = 0; ni < 8; ni++)
                    mma8(e[mi][ni], a[mi], bbf[ni]);
        }
    }
    __syncthreads();   // P fully consumed; Ss reusable as O^T scratch

    // ---- epilogue: scale by 1/rowsum, transpose via smem, coalesced out ----
    #pragma unroll
    for (int mi = 0; mi < 2; mi++) {
        int q = m0 + mi*16 + g;
        float rv0 = 1.0f / (psum[q]     + psum[128 + q]);
        float rv1 = 1.0f / (psum[q + 8] + psum[128 + q + 8]);
        #pragma unroll
        for (int ni = 0; ni < 8; ni++) {
            int c = c0 + ni*8 + 2*tt;
            Ss[c*132 + q]         = e[mi][ni][0] * rv0;
            Ss[(c+1)*132 + q]     = e[mi][ni][1] * rv0;
            Ss[c*132 + q + 8]     = e[mi][ni][2] * rv1;
            Ss[(c+1)*132 + q + 8] = e[mi][ni][3] * rv1;
        }
    }
    __syncthreads();

    const int tq  = qtile >> 1;
    const int hw0 = (qtile & 1) * 128;
    #pragma unroll
    for (int i = 0; i < 16; i++) {
        int idx = i*256 + tid;
        int c = idx >> 5, q4 = (idx & 31) * 4;
        float4 v = *(float4*)&Ss[c*132 + q4];
        *(float4*)&outR[(((size_t)(b*CH + c)*NT + t)*NT + tq)*NS + hw0 + q4] = v;
    }
}

// ---------------------------------------------------------------------------
extern "C" void kernel_launch(void* const* d_in, const int* in_sizes, int n_in,
                              void* d_out, int out_size)
{
    const float* x  = (const float*)d_in[0];
    const float* Wq = (const float*)d_in[1];
    const float* Wm = (const float*)d_in[2];
    const float* Wv = (const float*)d_in[3];
    float* out = (float*)d_out;

    const size_t R_SIZE = (size_t)NB * CH * NT * NT * NS;  // 33,554,432
    float* vout = out + R_SIZE;

    const int PROJ_SMEM = 64 * 128 * 2 * 4;  // 65536 B

    cudaFuncSetAttribute(proj_kernel, cudaFuncAttributeMaxDynamicSharedMemorySize, PROJ_SMEM);
    cudaFuncSetAttribute(attn_kernel, cudaFuncAttributeMaxDynamicSharedMemorySize, ATTN_SMEM);

    proj_kernel<<<dim3(32, 3, NB), 256, PROJ_SMEM>>>(x, Wq, Wm, Wv, vout);
    attn_kernel<<<dim3(32, NT, NB), 256, ATTN_SMEM>>>(out);
}

// round 4
// speedup vs baseline: 3.4137x; 1.6606x over previous
#include <cuda_runtime.h>

#define NB 4
#define CIN 256
#define CH 128      // C2
#define NT 16
#define NS 256      // spatial per frame
#define NP 4096     // T*S

// Scratch (device globals). Position-major [b][p][c], tf32-rounded.
// Q pre-scaled by 1/sqrt(128).
__device__ float g_Qt[(size_t)NB*NP*CH];
__device__ float g_Mt[(size_t)NB*NP*CH];
__device__ float g_Vt[(size_t)NB*NP*CH];

typedef unsigned int u32;

__device__ __forceinline__ u32 smem_u32(const void* p){
    u32 a;
    asm("{ .reg .u64 t; cvta.to.shared.u64 t, %1; cvt.u32.u64 %0, t; }"
        : "=r"(a) : "l"(p));
    return a;
}
__device__ __forceinline__ void cpa16(u32 dst, const void* src){
    asm volatile("cp.async.cg.shared.global [%0], [%1], 16;"
        :: "r"(dst), "l"(src));
}
__device__ __forceinline__ void cpcommit(){
    asm volatile("cp.async.commit_group;" ::: "memory");
}
template<int N> __device__ __forceinline__ void cpwait(){
    asm volatile("cp.async.wait_group %0;" :: "n"(N) : "memory");
}
__device__ __forceinline__ float cvt_tf32(float x){
    u32 r; asm("cvt.rna.tf32.f32 %0, %1;" : "=r"(r) : "f"(x));
    return __uint_as_float(r);
}
__device__ __forceinline__ u32 fb(float x){ return __float_as_uint(x); }

// m16n8k8 tf32 mma: D += A*B (row.col, f32 accum). Generic sm_80+ PTX.
__device__ __forceinline__ void mma8(float* d, const u32* a, const u32* b){
    asm volatile("mma.sync.aligned.m16n8k8.row.col.f32.tf32.tf32.f32 "
        "{%0,%1,%2,%3}, {%4,%5,%6,%7}, {%8,%9}, {%0,%1,%2,%3};"
        : "+f"(d[0]), "+f"(d[1]), "+f"(d[2]), "+f"(d[3])
        : "r"(a[0]), "r"(a[1]), "r"(a[2]), "r"(a[3]), "r"(b[0]), "r"(b[1]));
}

// ---------------------------------------------------------------------------
// Kernel A (tensorized): D[128p x 128o] = x^T * W^T per (ptile, proj, b).
// xs [64c][132p], ws [128o][68c]; 4 c-chunks; 2 CTAs/SM.
// ---------------------------------------------------------------------------
#define PJ_WS 8448
#define PROJ_SMEM ((8448 + 8704)*4)   // 68608 B

__global__ void __launch_bounds__(256, 2) proj_kernel(
    const float* __restrict__ x,
    const float* __restrict__ Wq,
    const float* __restrict__ Wm,
    const float* __restrict__ Wv,
    float* __restrict__ vout)
{
    extern __shared__ float sm[];
    float* xs = sm;
    float* ws = sm + PJ_WS;
    const u32 sx = smem_u32(sm);
    const u32 sw = smem_u32(sm + PJ_WS);

    const int b    = blockIdx.z;
    const int proj = blockIdx.y;
    const int p0   = blockIdx.x * 128;
    const float* W = (proj == 0) ? Wq : ((proj == 1) ? Wm : Wv);

    const int tid = threadIdx.x;
    const int w = tid >> 5, lane = tid & 31;
    const int g = lane >> 2, tt = lane & 3;
    const int m0 = (w >> 1) * 32;   // p tile
    const int c0 = (w & 1) * 64;    // o tile

    float acc[2][8][4];
    #pragma unroll
    for (int mi = 0; mi < 2; mi++)
        #pragma unroll
        for (int ni = 0; ni < 8; ni++)
            #pragma unroll
            for (int r = 0; r < 4; r++) acc[mi][ni][r] = 0.f;

    for (int ck = 0; ck < 4; ck++) {
        if (ck) __syncthreads();
        #pragma unroll
        for (int i = 0; i < 8; i++) {
            int idx = i*256 + tid;
            int r = idx >> 5, c4 = (idx & 31) * 4;
            cpa16(sx + (u32)(r*132 + c4)*4,
                  x + ((size_t)(b*CIN + ck*64 + r))*NP + p0 + c4);
        }
        #pragma unroll
        for (int i = 0; i < 8; i++) {
            int idx = i*256 + tid;
            int o = idx >> 4, c4 = (idx & 15) * 4;
            cpa16(sw + (u32)(o*68 + c4)*4, W + o*CIN + ck*64 + c4);
        }
        cpcommit(); cpwait<0>(); __syncthreads();

        #pragma unroll
        for (int k = 0; k < 8; k++) {
            u32 a[2][4], bb[8][2];
            #pragma unroll
            for (int mi = 0; mi < 2; mi++) {
                int p = m0 + mi*16 + g;
                a[mi][0] = fb(cvt_tf32(xs[(k*8+tt)*132 + p]));
                a[mi][1] = fb(cvt_tf32(xs[(k*8+tt)*132 + p + 8]));
                a[mi][2] = fb(cvt_tf32(xs[(k*8+tt+4)*132 + p]));
                a[mi][3] = fb(cvt_tf32(xs[(k*8+tt+4)*132 + p + 8]));
            }
            #pragma unroll
            for (int ni = 0; ni < 8; ni++) {
                int o = c0 + ni*8 + g;
                bb[ni][0] = fb(cvt_tf32(ws[o*68 + k*8 + tt]));
                bb[ni][1] = fb(cvt_tf32(ws[o*68 + k*8 + tt + 4]));
            }
            #pragma unroll
            for (int mi = 0; mi < 2; mi++)
                #pragma unroll
                for (int ni = 0; ni < 8; ni++)
                    mma8(acc[mi][ni], a[mi], bb[ni]);
        }
    }
    __syncthreads();

    if (proj < 2) {
        float* gdst = proj ? g_Mt : g_Qt;
        const float sc = proj ? 1.0f : 0.08838834764831845f;
        #pragma unroll
        for (int mi = 0; mi < 2; mi++) {
            int p = p0 + m0 + mi*16 + g;
            #pragma unroll
            for (int ni = 0; ni < 8; ni++) {
                int o = c0 + ni*8 + 2*tt;
                *(float2*)&gdst[((size_t)b*NP + p)*CH + o] =
                    make_float2(cvt_tf32(acc[mi][ni][0]*sc), cvt_tf32(acc[mi][ni][1]*sc));
                *(float2*)&gdst[((size_t)b*NP + p + 8)*CH + o] =
                    make_float2(cvt_tf32(acc[mi][ni][2]*sc), cvt_tf32(acc[mi][ni][3]*sc));
            }
        }
    } else {
        // g_Vt: tf32 position-major (B operand of PV GEMM)
        #pragma unroll
        for (int mi = 0; mi < 2; mi++) {
            int p = p0 + m0 + mi*16 + g;
            #pragma unroll
            for (int ni = 0; ni < 8; ni++) {
                int o = c0 + ni*8 + 2*tt;
                *(float2*)&g_Vt[((size_t)b*NP + p)*CH + o] =
                    make_float2(cvt_tf32(acc[mi][ni][0]), cvt_tf32(acc[mi][ni][1]));
                *(float2*)&g_Vt[((size_t)b*NP + p + 8)*CH + o] =
                    make_float2(cvt_tf32(acc[mi][ni][2]), cvt_tf32(acc[mi][ni][3]));
            }
        }
        // vout channel-major via smem transpose
        #pragma unroll
        for (int mi = 0; mi < 2; mi++) {
            int p = m0 + mi*16 + g;
            #pragma unroll
            for (int ni = 0; ni < 8; ni++) {
                int o = c0 + ni*8 + 2*tt;
                sm[o*132 + p]       = acc[mi][ni][0];
                sm[(o+1)*132 + p]   = acc[mi][ni][1];
                sm[o*132 + p+8]     = acc[mi][ni][2];
                sm[(o+1)*132 + p+8] = acc[mi][ni][3];
            }
        }
        __syncthreads();
        #pragma unroll
        for (int i = 0; i < 16; i++) {
            int idx = i*256 + tid;
            int o = idx >> 5, p4 = (idx & 31) * 4;
            *(float4*)&vout[((size_t)b*CH + o)*NP + p0 + p4] =
                *(float4*)&sm[o*132 + p4];
        }
    }
}

// ---------------------------------------------------------------------------
// Kernel B: attention. Ss is [256s][132q]; each 64-key chunk's M tile is
// prefetched INTO its own future S block (4-deep cp.async). V double-buffers
// in the dead Q region (32-row chunks).
// ---------------------------------------------------------------------------
#define A_SS 16384
#define A_PM 50176
#define A_GM 51200
#define A_PS 51328
#define A_RS 52352
#define ATTN_SMEM (52480*4)   // 209920 B
#define VBUF 4352             // floats per V buffer (32 x 136)

__global__ void __launch_bounds__(256) attn_kernel(float* __restrict__ outR)
{
    extern __shared__ float sm[];
    float* Qs = sm;
    float* Ss = sm + A_SS;
    const u32 sq = smem_u32(sm);
    const u32 ss = smem_u32(sm + A_SS);

    const int tid = threadIdx.x;
    const int w = tid >> 5, lane = tid & 31;
    const int g = lane >> 2, tt = lane & 3;
    const int qtile = blockIdx.x, t = blockIdx.y, b = blockIdx.z;
    const int q0 = qtile * 128;

    const int m0 = (w >> 1) * 32;
    const int n0 = (w & 1) * 32;
    const int c0 = (w & 1) * 64;

    const float* gq = g_Qt + ((size_t)b*NP + q0)*CH;
    const float* gm = g_Mt + ((size_t)b*NP + t*NS)*CH;
    const float* gv = g_Vt + ((size_t)b*NP + t*NS)*CH;

    // ---- issue Q + M0 (group0), then M1, M2, M3 ----
    #pragma unroll
    for (int i = 0; i < 16; i++) {
        int idx = i*256 + tid;
        int q = idx >> 5, c4 = (idx & 31) * 4;
        cpa16(sq + (u32)(q*128 + (c4 ^ ((q & 7) << 2)))*4, gq + q*CH + c4);
    }
    #pragma unroll
    for (int j = 0; j < 4; j++) {
        #pragma unroll
        for (int i = 0; i < 8; i++) {
            int idx = i*256 + tid;
            int s = idx >> 5, c4 = (idx & 31) * 4;
            cpa16(ss + (u32)((64*j + s)*132 + c4)*4, gm + (size_t)(64*j + s)*CH + c4);
        }
        cpcommit();
    }

    // ---- GEMM1: S[s][q] per 64-key chunk ----
    #pragma unroll
    for (int j = 0; j < 4; j++) {
        if (j == 0) cpwait<3>(); else if (j == 1) cpwait<2>();
        else if (j == 2) cpwait<1>(); else cpwait<0>();
        __syncthreads();

        float d[2][4][4];
        #pragma unroll
        for (int mi = 0; mi < 2; mi++)
            #pragma unroll
            for (int ni = 0; ni < 4; ni++)
                #pragma unroll
                for (int r = 0; r < 4; r++) d[mi][ni][r] = 0.f;

        #pragma unroll
        for (int k = 0; k < 16; k++) {
            u32 a[2][4], bb[4][2];
            #pragma unroll
            for (int mi = 0; mi < 2; mi++) {
                int q = m0 + mi*16 + g;
                int swz = (q & 7) << 2;
                int c = k*8 + tt;
                a[mi][0] = fb(Qs[q*128     + (c ^ swz)]);
                a[mi][1] = fb(Qs[(q+8)*128 + (c ^ swz)]);
                a[mi][2] = fb(Qs[q*128     + ((c+4) ^ swz)]);
                a[mi][3] = fb(Qs[(q+8)*128 + ((c+4) ^ swz)]);
            }
            #pragma unroll
            for (int ni = 0; ni < 4; ni++) {
                int srow = 64*j + n0 + ni*8 + g;
                bb[ni][0] = fb(Ss[srow*132 + k*8 + tt]);
                bb[ni][1] = fb(Ss[srow*132 + k*8 + tt + 4]);
            }
            #pragma unroll
            for (int mi = 0; mi < 2; mi++)
                #pragma unroll
                for (int ni = 0; ni < 4; ni++)
                    mma8(d[mi][ni], a[mi], bb[ni]);
        }
        __syncthreads();   // all warps done reading M block j (and Qs at j=3)

        if (j == 3) {      // Qs dead: prefetch V chunks 0,1
            #pragma unroll
            for (int vj = 0; vj < 2; vj++) {
                #pragma unroll
                for (int i = 0; i < 4; i++) {
                    int idx = i*256 + tid;
                    int s = idx >> 5, c4 = (idx & 31) * 4;
                    cpa16(sq + (u32)(vj*VBUF + s*136 + c4)*4,
                          gv + (size_t)(32*vj + s)*CH + c4);
                }
                cpcommit();
            }
        }

        // store S fragments into block j (scalar, conflict-free)
        #pragma unroll
        for (int mi = 0; mi < 2; mi++) {
            int q = m0 + mi*16 + g;
            #pragma unroll
            for (int ni = 0; ni < 4; ni++) {
                int srow = 64*j + n0 + ni*8 + 2*tt;
                Ss[srow*132 + q]         = d[mi][ni][0];
                Ss[(srow+1)*132 + q]     = d[mi][ni][1];
                Ss[srow*132 + q + 8]     = d[mi][ni][2];
                Ss[(srow+1)*132 + q + 8] = d[mi][ni][3];
            }
        }
    }
    __syncthreads();

    // ---- softmax over 256 s per q (warp-per-rows, float4 along q) ----
    float* pm = sm + A_PM;
    float* gmv = sm + A_GM;
    float* ps = sm + A_PS;
    float* rs = sm + A_RS;
    {
        const int r0 = w * 32;
        float4 mx = make_float4(-3e38f, -3e38f, -3e38f, -3e38f);
        #pragma unroll 8
        for (int r = 0; r < 32; r++) {
            float4 v = *(float4*)&Ss[(r0 + r)*132 + lane*4];
            mx.x = fmaxf(mx.x, v.x); mx.y = fmaxf(mx.y, v.y);
            mx.z = fmaxf(mx.z, v.z); mx.w = fmaxf(mx.w, v.w);
        }
        *(float4*)&pm[w*128 + lane*4] = mx;
        __syncthreads();
        if (tid < 128) {
            float m = pm[tid];
            #pragma unroll
            for (int w2 = 1; w2 < 8; w2++) m = fmaxf(m, pm[w2*128 + tid]);
            gmv[tid] = m;
        }
        __syncthreads();
        float4 gx = *(float4*)&gmv[lane*4];
        float4 sum = make_float4(0.f, 0.f, 0.f, 0.f);
        #pragma unroll 4
        for (int r = 0; r < 32; r++) {
            float4* p = (float4*)&Ss[(r0 + r)*132 + lane*4];
            float4 v = *p;
            float e0 = __expf(v.x - gx.x), e1 = __expf(v.y - gx.y);
            float e2 = __expf(v.z - gx.z), e3 = __expf(v.w - gx.w);
            sum.x += e0; sum.y += e1; sum.z += e2; sum.w += e3;
            v.x = cvt_tf32(e0); v.y = cvt_tf32(e1);
            v.z = cvt_tf32(e2); v.w = cvt_tf32(e3);
            *p = v;
        }
        *(float4*)&ps[w*128 + lane*4] = sum;
        __syncthreads();
        if (tid < 128) {
            float s_ = 0.f;
            #pragma unroll
            for (int w2 = 0; w2 < 8; w2++) s_ += ps[w2*128 + tid];
            rs[tid] = 1.0f / s_;
        }
    }

    // ---- GEMM2: O += P * V over 8 chunks of 32 s, double-buffered V ----
    float e[2][8][4];
    #pragma unroll
    for (int mi = 0; mi < 2; mi++)
        #pragma unroll
        for (int ni = 0; ni < 8; ni++)
            #pragma unroll
            for (int r = 0; r < 4; r++) e[mi][ni][r] = 0.f;

    #pragma unroll
    for (int j = 0; j < 8; j++) {
        if (j == 7) cpwait<0>(); else cpwait<1>();
        __syncthreads();
        const float* VB = Qs + (j & 1) * VBUF;

        #pragma unroll
        for (int k = 0; k < 4; k++) {
            u32 a[2][4], bb[8][2];
            #pragma unroll
            for (int mi = 0; mi < 2; mi++) {
                int q = m0 + mi*16 + g;
                int sr = j*32 + k*8 + tt;
                a[mi][0] = fb(Ss[sr*132 + q]);
                a[mi][1] = fb(Ss[sr*132 + q + 8]);
                a[mi][2] = fb(Ss[(sr+4)*132 + q]);
                a[mi][3] = fb(Ss[(sr+4)*132 + q + 8]);
            }
            #pragma unroll
            for (int ni = 0; ni < 8; ni++) {
                int c = c0 + ni*8 + g;
                bb[ni][0] = fb(VB[(k*8+tt)*136 + c]);
                bb[ni][1] = fb(VB[(k*8+tt+4)*136 + c]);
            }
            #pragma unroll
            for (int mi = 0; mi < 2; mi++)
                #pragma unroll
                for (int ni = 0; ni < 8; ni++)
                    mma8(e[mi][ni], a[mi], bb[ni]);
        }
        __syncthreads();   // all warps done reading VB

        if (j + 2 < 8) {
            #pragma unroll
            for (int i = 0; i < 4; i++) {
                int idx = i*256 + tid;
                int s = idx >> 5, c4 = (idx & 31) * 4;
                cpa16(sq + (u32)((j & 1)*VBUF + s*136 + c4)*4,
                      gv + (size_t)(32*(j+2) + s)*CH + c4);
            }
            cpcommit();
        }
    }

    // ---- epilogue: normalize, transpose via Ss, coalesced writes ----
    #pragma unroll
    for (int mi = 0; mi < 2; mi++) {
        int q = m0 + mi*16 + g;
        float rv0 = rs[q], rv1 = rs[q + 8];
        #pragma unroll
        for (int ni = 0; ni < 8; ni++) {
            int c = c0 + ni*8 + 2*tt;
            Ss[c*132 + q]         = e[mi][ni][0] * rv0;
            Ss[(c+1)*132 + q]     = e[mi][ni][1] * rv0;
            Ss[c*132 + q + 8]     = e[mi][ni][2] * rv1;
            Ss[(c+1)*132 + q + 8] = e[mi][ni][3] * rv1;
        }
    }
    __syncthreads();

    const int tq  = qtile >> 1;
    const int hw0 = (qtile & 1) * 128;
    #pragma unroll
    for (int i = 0; i < 16; i++) {
        int idx = i*256 + tid;
        int c = idx >> 5, q4 = (idx & 31) * 4;
        *(float4*)&outR[(((size_t)(b*CH + c)*NT + t)*NT + tq)*NS + hw0 + q4] =
            *(float4*)&Ss[c*132 + q4];
    }
}

// ---------------------------------------------------------------------------
extern "C" void kernel_launch(void* const* d_in, const int* in_sizes, int n_in,
                              void* d_out, int out_size)
{
    const float* x  = (const float*)d_in[0];
    const float* Wq = (const float*)d_in[1];
    const float* Wm = (const float*)d_in[2];
    const float* Wv = (const float*)d_in[3];
    float* out = (float*)d_out;

    const size_t R_SIZE = (size_t)NB * CH * NT * NT * NS;  // 33,554,432
    float* vout = out + R_SIZE;

    cudaFuncSetAttribute(proj_kernel, cudaFuncAttributeMaxDynamicSharedMemorySize, PROJ_SMEM);
    cudaFuncSetAttribute(attn_kernel, cudaFuncAttributeMaxDynamicSharedMemorySize, ATTN_SMEM);

    proj_kernel<<<dim3(32, 3, NB), 256, PROJ_SMEM>>>(x, Wq, Wm, Wv, vout);
    attn_kernel<<<dim3(32, NT, NB), 256, ATTN_SMEM>>>(out);
}